// round 1
// baseline (speedup 1.0000x reference)
#include <cuda_runtime.h>
#include <math.h>

#define NN   50000
#define NE   600000
#define NET  650000   // NE + NN self loops
#define HID  128

// ---------------- device scratch (no allocations allowed) ----------------
__device__ int   g_is64;
__device__ int   g_src[NET];
__device__ int   g_dst[NET];
__device__ int   g_deg[NN];
__device__ int   g_rowptr[NN + 1];
__device__ int   g_pos[NN];
__device__ int   g_csrc[NET];
__device__ float g_h[NN * HID];
__device__ float g_o[NN * HID];
__device__ float g_ssrc[NN];
__device__ float g_sdst[NN];

// ---------------- dtype detection for edge_index (int32 vs int64) --------
// If int64: values < 50000 => every odd 32-bit word is zero.
__global__ void k_detect(const unsigned* __restrict__ w) {
    __shared__ int nz;
    if (threadIdx.x == 0) nz = 0;
    __syncthreads();
    for (int i = threadIdx.x; i < 1024; i += blockDim.x)
        if (w[2 * i + 1] != 0u) atomicAdd(&nz, 1);
    __syncthreads();
    if (threadIdx.x == 0) g_is64 = (nz == 0) ? 1 : 0;
}

__global__ void k_zero_deg() {
    int i = blockIdx.x * blockDim.x + threadIdx.x;
    if (i < NN) g_deg[i] = 0;
}

// build src/dst arrays (incl. self loops) + degree histogram on dst
__global__ void k_build(const void* __restrict__ ed) {
    int i = blockIdx.x * blockDim.x + threadIdx.x;
    if (i >= NET) return;
    int s, d;
    if (i < NE) {
        if (g_is64) {
            const long long* p = (const long long*)ed;
            s = (int)p[i];
            d = (int)p[NE + i];
        } else {
            const int* p = (const int*)ed;
            s = p[i];
            d = p[NE + i];
        }
    } else {
        s = d = i - NE;
    }
    g_src[i] = s;
    g_dst[i] = d;
    atomicAdd(&g_deg[d], 1);
}

// single-block exclusive scan of g_deg -> g_rowptr / g_pos
__global__ void k_scan() {
    __shared__ int sm[1024];
    __shared__ int carry;
    int t = threadIdx.x;
    if (t == 0) carry = 0;
    for (int base = 0; base < NN; base += 1024) {
        __syncthreads();
        int c = carry;
        int v = (base + t < NN) ? g_deg[base + t] : 0;
        sm[t] = v;
        __syncthreads();
        for (int off = 1; off < 1024; off <<= 1) {
            int x = (t >= off) ? sm[t - off] : 0;
            __syncthreads();
            sm[t] += x;
            __syncthreads();
        }
        int incl = sm[t];
        if (base + t < NN) {
            g_rowptr[base + t] = c + incl - v;
            g_pos[base + t]    = c + incl - v;
        }
        __syncthreads();
        if (t == 0) carry = c + sm[1023];
    }
    __syncthreads();
    if (t == 0) g_rowptr[NN] = carry;
}

__global__ void k_fill() {
    int i = blockIdx.x * blockDim.x + threadIdx.x;
    if (i >= NET) return;
    int d = g_dst[i];
    int slot = atomicAdd(&g_pos[d], 1);
    g_csrc[slot] = g_src[i];
}

// ---------------- SGEMM: C[M,N] = A[M,K] @ B[K,N] (+ optional bias) ------
// 64x64 block tile, 4x4 micro tile, 256 threads, BK=8.
__global__ void __launch_bounds__(256)
k_sgemm(const float* __restrict__ A, const float* __restrict__ B,
        const float* __restrict__ bias, float* __restrict__ C,
        int M, int K, int N) {
    __shared__ __align__(16) float As[8][64];
    __shared__ __align__(16) float Bs[8][64];

    int tid = threadIdx.x;
    int tx = tid & 15;        // 0..15 -> 4 cols each
    int ty = tid >> 4;        // 0..15 -> 4 rows each
    int row0 = blockIdx.y * 64;
    int col0 = blockIdx.x * 64;

    float acc[4][4];
#pragma unroll
    for (int i = 0; i < 4; i++)
#pragma unroll
        for (int j = 0; j < 4; j++) acc[i][j] = 0.f;

    for (int kk = 0; kk < K; kk += 8) {
        // load A tile: threads 0..127 each load float4 (row, k..k+3)
        if (tid < 128) {
            int row = tid >> 1;
            int kq  = (tid & 1) * 4;
            float4 av = make_float4(0.f, 0.f, 0.f, 0.f);
            int gr = row0 + row;
            if (gr < M)
                av = *(const float4*)(A + (size_t)gr * K + kk + kq);
            As[kq + 0][row] = av.x;
            As[kq + 1][row] = av.y;
            As[kq + 2][row] = av.z;
            As[kq + 3][row] = av.w;
        } else {
            int j = tid - 128;
            int k  = j >> 4;
            int c4 = (j & 15) * 4;
            float4 bv = *(const float4*)(B + (size_t)(kk + k) * N + col0 + c4);
            *(float4*)&Bs[k][c4] = bv;
        }
        __syncthreads();
#pragma unroll
        for (int k = 0; k < 8; k++) {
            float4 a = *(const float4*)&As[k][ty * 4];
            float4 b = *(const float4*)&Bs[k][tx * 4];
            float av[4] = {a.x, a.y, a.z, a.w};
            float bv[4] = {b.x, b.y, b.z, b.w};
#pragma unroll
            for (int i = 0; i < 4; i++)
#pragma unroll
                for (int j = 0; j < 4; j++)
                    acc[i][j] += av[i] * bv[j];
        }
        __syncthreads();
    }

    float4 b4 = make_float4(0.f, 0.f, 0.f, 0.f);
    if (bias) b4 = *(const float4*)(bias + col0 + tx * 4);
#pragma unroll
    for (int i = 0; i < 4; i++) {
        int gr = row0 + ty * 4 + i;
        if (gr < M) {
            float4 v;
            v.x = acc[i][0] + b4.x;
            v.y = acc[i][1] + b4.y;
            v.z = acc[i][2] + b4.z;
            v.w = acc[i][3] + b4.w;
            *(float4*)(C + (size_t)gr * N + col0 + tx * 4) = v;
        }
    }
}

// ---------------- per-node attention scores ------------------------------
// warp per node: ssrc = <h_v, a_src>, sdst = <h_v, a_dst>
__global__ void __launch_bounds__(256)
k_scores(const float* __restrict__ h, const float* __restrict__ as_,
         const float* __restrict__ ad_) {
    int warp = (blockIdx.x * blockDim.x + threadIdx.x) >> 5;
    int lane = threadIdx.x & 31;
    if (warp >= NN) return;
    float4 hv = *(const float4*)(h + (size_t)warp * HID + lane * 4);
    float4 a4 = *(const float4*)(as_ + lane * 4);
    float4 d4 = *(const float4*)(ad_ + lane * 4);
    float ps = hv.x * a4.x + hv.y * a4.y + hv.z * a4.z + hv.w * a4.w;
    float pd = hv.x * d4.x + hv.y * d4.y + hv.z * d4.z + hv.w * d4.w;
#pragma unroll
    for (int off = 16; off; off >>= 1) {
        ps += __shfl_xor_sync(0xFFFFFFFFu, ps, off);
        pd += __shfl_xor_sync(0xFFFFFFFFu, pd, off);
    }
    if (lane == 0) {
        g_ssrc[warp] = ps;
        g_sdst[warp] = pd;
    }
}

// ---------------- GAT aggregation: warp per dst node, online softmax -----
// out[v] = leaky_relu( sum_e alpha_e * h[src_e] + b , 0.01 )
__global__ void __launch_bounds__(256)
k_agg(const float* __restrict__ h, const float* __restrict__ bias,
      float* __restrict__ out) {
    int warp = (blockIdx.x * blockDim.x + threadIdx.x) >> 5;
    int lane = threadIdx.x & 31;
    if (warp >= NN) return;

    int beg = g_rowptr[warp];
    int end = g_rowptr[warp + 1];
    float sdst = g_sdst[warp];

    float m = -INFINITY;
    float den = 0.f;
    float4 acc = make_float4(0.f, 0.f, 0.f, 0.f);

    for (int i = beg; i < end; i++) {
        int s = g_csrc[i];
        float e = g_ssrc[s] + sdst;
        e = (e > 0.f) ? e : 0.2f * e;           // attention LeakyReLU
        float mn = fmaxf(m, e);
        float sc = __expf(m - mn);              // 0 on first iter (m=-inf)
        float we = __expf(e - mn);
        den = den * sc + we;
        float4 hv = *(const float4*)(h + (size_t)s * HID + lane * 4);
        acc.x = acc.x * sc + we * hv.x;
        acc.y = acc.y * sc + we * hv.y;
        acc.z = acc.z * sc + we * hv.z;
        acc.w = acc.w * sc + we * hv.w;
        m = mn;
    }

    float inv = 1.f / (den + 1e-16f);
    float4 b4 = *(const float4*)(bias + lane * 4);
    float4 v;
    v.x = acc.x * inv + b4.x;
    v.y = acc.y * inv + b4.y;
    v.z = acc.z * inv + b4.z;
    v.w = acc.w * inv + b4.w;
    // inter-layer LeakyReLU(0.01) — applied after every GAT layer
    v.x = (v.x > 0.f) ? v.x : 0.01f * v.x;
    v.y = (v.y > 0.f) ? v.y : 0.01f * v.y;
    v.z = (v.z > 0.f) ? v.z : 0.01f * v.z;
    v.w = (v.w > 0.f) ? v.w : 0.01f * v.w;
    *(float4*)(out + (size_t)warp * HID + lane * 4) = v;
}

// ---------------- launch -------------------------------------------------
extern "C" void kernel_launch(void* const* d_in, const int* in_sizes, int n_in,
                              void* d_out, int out_size) {
    (void)in_sizes; (void)n_in; (void)out_size;

    const float* x    = (const float*)d_in[0];
    const void*  eidx = d_in[1];

    float *p_h, *p_o;
    cudaGetSymbolAddress((void**)&p_h, g_h);
    cudaGetSymbolAddress((void**)&p_o, g_o);

    // CSR build (once; reused by all 3 layers)
    k_detect<<<1, 256>>>((const unsigned*)eidx);
    k_zero_deg<<<(NN + 255) / 256, 256>>>();
    k_build<<<(NET + 255) / 256, 256>>>(eidx);
    k_scan<<<1, 1024>>>();
    k_fill<<<(NET + 255) / 256, 256>>>();

    const int gridM = (NN + 63) / 64;          // 782
    const int nodeBlocks = NN / 8;             // 6250 blocks * 8 warps = 50000

    const float* cur = x;
    int fin = 64;
    for (int L = 0; L < 3; L++) {
        const float* W  = (const float*)d_in[2 + 4 * L];
        const float* as_ = (const float*)d_in[3 + 4 * L];
        const float* ad_ = (const float*)d_in[4 + 4 * L];
        const float* b  = (const float*)d_in[5 + 4 * L];

        k_sgemm<<<dim3(HID / 64, gridM), 256>>>(cur, W, nullptr, p_h,
                                                NN, fin, HID);
        k_scores<<<nodeBlocks, 256>>>(p_h, as_, ad_);
        k_agg<<<nodeBlocks, 256>>>(p_h, b, p_o);

        cur = p_o;
        fin = HID;
    }

    const float* Wout = (const float*)d_in[14];
    const float* bout = (const float*)d_in[15];
    k_sgemm<<<dim3(64 / 64, gridM), 256>>>(p_o, Wout, bout, (float*)d_out,
                                           NN, HID, 64);
}

// round 2
// speedup vs baseline: 1.2040x; 1.2040x over previous
#include <cuda_runtime.h>
#include <math.h>

#define NN   50000
#define NE   600000
#define NET  650000   // NE + NN self loops
#define HID  128

// ---------------- device scratch (no allocations allowed) ----------------
__device__ int   g_is64;
__device__ int   g_counter;
__device__ int   g_src[NET];
__device__ int   g_dst[NET];
__device__ int   g_deg[NN];
__device__ int   g_beg[NN];
__device__ int   g_pos[NN];
__device__ int   g_csrc[NET];
__device__ float g_h[NN * HID];
__device__ float g_o[NN * HID];
__device__ float g_ssrc[3][NN];
__device__ float g_sdst[3][NN];

// ---------------- dtype detection for edge_index (int32 vs int64) --------
// If int64: values < 50000 => every odd 32-bit word is zero.
__global__ void k_detect(const unsigned* __restrict__ w) {
    __shared__ int nz;
    if (threadIdx.x == 0) nz = 0;
    __syncthreads();
    for (int i = threadIdx.x; i < 1024; i += blockDim.x)
        if (w[2 * i + 1] != 0u) atomicAdd(&nz, 1);
    __syncthreads();
    if (threadIdx.x == 0) g_is64 = (nz == 0) ? 1 : 0;
}

// zero degree histogram, warp-allocator counter, and all score buffers
__global__ void k_zero_all() {
    int i = blockIdx.x * blockDim.x + threadIdx.x;
    if (i < NN) {
        g_deg[i] = 0;
#pragma unroll
        for (int l = 0; l < 3; l++) {
            g_ssrc[l][i] = 0.f;
            g_sdst[l][i] = 0.f;
        }
    }
    if (i == 0) g_counter = 0;
}

// build src/dst arrays (incl. self loops) + degree histogram on dst
__global__ void k_build(const void* __restrict__ ed) {
    int i = blockIdx.x * blockDim.x + threadIdx.x;
    if (i >= NET) return;
    int s, d;
    if (i < NE) {
        if (g_is64) {
            const long long* p = (const long long*)ed;
            s = (int)p[i];
            d = (int)p[NE + i];
        } else {
            const int* p = (const int*)ed;
            s = p[i];
            d = p[NE + i];
        }
    } else {
        s = d = i - NE;
    }
    g_src[i] = s;
    g_dst[i] = d;
    atomicAdd(&g_deg[d], 1);
}

// warp-aggregated segment allocation: each node gets a contiguous range
// [beg, beg+deg). Segment ORDER is nondeterministic (atomic base), but each
// launch is self-consistent: fill and agg both use the same beg written here.
__global__ void k_alloc() {
    int i = blockIdx.x * blockDim.x + threadIdx.x;
    int lane = threadIdx.x & 31;
    int v = (i < NN) ? g_deg[i] : 0;
    int incl = v;
#pragma unroll
    for (int off = 1; off < 32; off <<= 1) {
        int x = __shfl_up_sync(0xFFFFFFFFu, incl, off);
        if (lane >= off) incl += x;
    }
    int wsum = __shfl_sync(0xFFFFFFFFu, incl, 31);
    int base = 0;
    if (lane == 31) base = atomicAdd(&g_counter, wsum);
    base = __shfl_sync(0xFFFFFFFFu, base, 31);
    if (i < NN) {
        int b = base + incl - v;
        g_beg[i] = b;
        g_pos[i] = b;
    }
}

__global__ void k_fill() {
    int i = blockIdx.x * blockDim.x + threadIdx.x;
    if (i >= NET) return;
    int d = g_dst[i];
    int slot = atomicAdd(&g_pos[d], 1);
    g_csrc[slot] = g_src[i];
}

// ---------------- SGEMM: C[M,N] = A[M,K] @ B[K,N] (+ optional bias) ------
// 64x64 block tile, 4x4 micro tile, 256 threads, BK=8.
// Optional fused per-row attention scores: ssrc[r] += <C_row, a_s>, etc.
__global__ void __launch_bounds__(256)
k_sgemm(const float* __restrict__ A, const float* __restrict__ B,
        const float* __restrict__ bias, float* __restrict__ C,
        int M, int K, int N,
        float* __restrict__ ssrc, float* __restrict__ sdst,
        const float* __restrict__ a_s, const float* __restrict__ a_d) {
    __shared__ __align__(16) float As[8][64];
    __shared__ __align__(16) float Bs[8][64];

    int tid = threadIdx.x;
    int tx = tid & 15;        // 0..15 -> 4 cols each
    int ty = tid >> 4;        // 0..15 -> 4 rows each
    int row0 = blockIdx.y * 64;
    int col0 = blockIdx.x * 64;

    float acc[4][4];
#pragma unroll
    for (int i = 0; i < 4; i++)
#pragma unroll
        for (int j = 0; j < 4; j++) acc[i][j] = 0.f;

    for (int kk = 0; kk < K; kk += 8) {
        if (tid < 128) {
            int row = tid >> 1;
            int kq  = (tid & 1) * 4;
            float4 av = make_float4(0.f, 0.f, 0.f, 0.f);
            int gr = row0 + row;
            if (gr < M)
                av = *(const float4*)(A + (size_t)gr * K + kk + kq);
            As[kq + 0][row] = av.x;
            As[kq + 1][row] = av.y;
            As[kq + 2][row] = av.z;
            As[kq + 3][row] = av.w;
        } else {
            int j = tid - 128;
            int k  = j >> 4;
            int c4 = (j & 15) * 4;
            float4 bv = *(const float4*)(B + (size_t)(kk + k) * N + col0 + c4);
            *(float4*)&Bs[k][c4] = bv;
        }
        __syncthreads();
#pragma unroll
        for (int k = 0; k < 8; k++) {
            float4 a = *(const float4*)&As[k][ty * 4];
            float4 b = *(const float4*)&Bs[k][tx * 4];
            float av[4] = {a.x, a.y, a.z, a.w};
            float bv[4] = {b.x, b.y, b.z, b.w};
#pragma unroll
            for (int i = 0; i < 4; i++)
#pragma unroll
                for (int j = 0; j < 4; j++)
                    acc[i][j] += av[i] * bv[j];
        }
        __syncthreads();
    }

    float4 b4 = make_float4(0.f, 0.f, 0.f, 0.f);
    if (bias) b4 = *(const float4*)(bias + col0 + tx * 4);
#pragma unroll
    for (int i = 0; i < 4; i++) {
        int gr = row0 + ty * 4 + i;
        if (gr < M) {
            float4 v;
            v.x = acc[i][0] + b4.x;
            v.y = acc[i][1] + b4.y;
            v.z = acc[i][2] + b4.z;
            v.w = acc[i][3] + b4.w;
            *(float4*)(C + (size_t)gr * N + col0 + tx * 4) = v;
        }
    }

    // fused attention score partials (scores use pre-bias h; bias==nullptr here)
    if (ssrc) {
        float4 asv = *(const float4*)(a_s + col0 + tx * 4);
        float4 adv = *(const float4*)(a_d + col0 + tx * 4);
#pragma unroll
        for (int i = 0; i < 4; i++) {
            float ps = acc[i][0] * asv.x + acc[i][1] * asv.y +
                       acc[i][2] * asv.z + acc[i][3] * asv.w;
            float pd = acc[i][0] * adv.x + acc[i][1] * adv.y +
                       acc[i][2] * adv.z + acc[i][3] * adv.w;
#pragma unroll
            for (int off = 8; off; off >>= 1) {
                ps += __shfl_xor_sync(0xFFFFFFFFu, ps, off);
                pd += __shfl_xor_sync(0xFFFFFFFFu, pd, off);
            }
            if (tx == 0) {
                int gr = row0 + ty * 4 + i;
                if (gr < M) {
                    atomicAdd(&ssrc[gr], ps);
                    atomicAdd(&sdst[gr], pd);
                }
            }
        }
    }
}

// ---------------- GAT aggregation: warp per dst node, online softmax -----
// out[v] = leaky_relu( sum_e alpha_e * h[src_e] + b , 0.01 )
__global__ void __launch_bounds__(256)
k_agg(const float* __restrict__ h, const float* __restrict__ bias,
      float* __restrict__ out,
      const float* __restrict__ ssrc, const float* __restrict__ sdst) {
    int warp = (blockIdx.x * blockDim.x + threadIdx.x) >> 5;
    int lane = threadIdx.x & 31;
    if (warp >= NN) return;

    int beg = g_beg[warp];
    int end = beg + g_deg[warp];
    float sd = sdst[warp];

    float m = -INFINITY;
    float den = 0.f;
    float4 acc = make_float4(0.f, 0.f, 0.f, 0.f);

    for (int i = beg; i < end; i++) {
        int s = g_csrc[i];
        float e = ssrc[s] + sd;
        e = (e > 0.f) ? e : 0.2f * e;           // attention LeakyReLU
        float mn = fmaxf(m, e);
        float sc = __expf(m - mn);              // 0 on first iter (m=-inf)
        float we = __expf(e - mn);
        den = den * sc + we;
        float4 hv = *(const float4*)(h + (size_t)s * HID + lane * 4);
        acc.x = acc.x * sc + we * hv.x;
        acc.y = acc.y * sc + we * hv.y;
        acc.z = acc.z * sc + we * hv.z;
        acc.w = acc.w * sc + we * hv.w;
        m = mn;
    }

    float inv = 1.f / (den + 1e-16f);
    float4 b4 = *(const float4*)(bias + lane * 4);
    float4 v;
    v.x = acc.x * inv + b4.x;
    v.y = acc.y * inv + b4.y;
    v.z = acc.z * inv + b4.z;
    v.w = acc.w * inv + b4.w;
    // inter-layer LeakyReLU(0.01)
    v.x = (v.x > 0.f) ? v.x : 0.01f * v.x;
    v.y = (v.y > 0.f) ? v.y : 0.01f * v.y;
    v.z = (v.z > 0.f) ? v.z : 0.01f * v.z;
    v.w = (v.w > 0.f) ? v.w : 0.01f * v.w;
    *(float4*)(out + (size_t)warp * HID + lane * 4) = v;
}

// ---------------- launch -------------------------------------------------
extern "C" void kernel_launch(void* const* d_in, const int* in_sizes, int n_in,
                              void* d_out, int out_size) {
    (void)in_sizes; (void)n_in; (void)out_size;

    const float* x    = (const float*)d_in[0];
    const void*  eidx = d_in[1];

    float *p_h, *p_o, *p_ss, *p_sd;
    cudaGetSymbolAddress((void**)&p_h, g_h);
    cudaGetSymbolAddress((void**)&p_o, g_o);
    cudaGetSymbolAddress((void**)&p_ss, g_ssrc);
    cudaGetSymbolAddress((void**)&p_sd, g_sdst);

    // CSR build (once; reused by all 3 layers)
    k_detect<<<1, 256>>>((const unsigned*)eidx);
    k_zero_all<<<(NN + 255) / 256, 256>>>();
    k_build<<<(NET + 255) / 256, 256>>>(eidx);
    k_alloc<<<(NN + 255) / 256, 256>>>();
    k_fill<<<(NET + 255) / 256, 256>>>();

    const int gridM = (NN + 63) / 64;          // 782
    const int nodeBlocks = NN / 8;             // 6250 blocks * 8 warps = 50000

    const float* cur = x;
    int fin = 64;
    for (int L = 0; L < 3; L++) {
        const float* W   = (const float*)d_in[2 + 4 * L];
        const float* as_ = (const float*)d_in[3 + 4 * L];
        const float* ad_ = (const float*)d_in[4 + 4 * L];
        const float* b   = (const float*)d_in[5 + 4 * L];
        float* ss = p_ss + (size_t)L * NN;
        float* sd = p_sd + (size_t)L * NN;

        k_sgemm<<<dim3(HID / 64, gridM), 256>>>(cur, W, nullptr, p_h,
                                                NN, fin, HID,
                                                ss, sd, as_, ad_);
        k_agg<<<nodeBlocks, 256>>>(p_h, b, p_o, ss, sd);

        cur = p_o;
        fin = HID;
    }

    const float* Wout = (const float*)d_in[14];
    const float* bout = (const float*)d_in[15];
    k_sgemm<<<dim3(64 / 64, gridM), 256>>>(p_o, Wout, bout, (float*)d_out,
                                           NN, HID, 64,
                                           nullptr, nullptr, nullptr, nullptr);
}

// round 4
// speedup vs baseline: 1.7524x; 1.4556x over previous
#include <cuda_runtime.h>
#include <cuda_bf16.h>
#include <math.h>
#include <stdint.h>

#define NN   50000
#define NE   600000
#define NET  650000   // NE + NN self loops
#define HID  128

// ---------------- device scratch (no allocations allowed) ----------------
__device__ int   g_is64;
__device__ int   g_counter;
__device__ int   g_src[NET];
__device__ int   g_dst[NET];
__device__ int   g_deg[NN];
__device__ int   g_beg[NN];
__device__ int   g_pos[NN];
__device__ int   g_csrc[NET];
__device__ float g_h[NN * HID];
__device__ float g_o[NN * HID];
__device__ float g_ssrc[3][NN];
__device__ float g_sdst[3][NN];
// pre-split, pre-transposed weights: [layer][n*K + k], bf16 hi/lo
__device__ __align__(16) __nv_bfloat16 g_wthi[4][128 * 128];
__device__ __align__(16) __nv_bfloat16 g_wtlo[4][128 * 128];

// ---------------- weight prep: split fp32 W[K,N] -> bf16 hi/lo W^T[N,K] ---
__global__ void k_prepw(const float* __restrict__ W0, const float* __restrict__ W1,
                        const float* __restrict__ W2, const float* __restrict__ W3) {
    int l = blockIdx.y;
    const int Ks[4] = {64, 128, 128, 128};
    const int Ns[4] = {128, 128, 128, 64};
    const float* W = (l == 0) ? W0 : (l == 1) ? W1 : (l == 2) ? W2 : W3;
    int K = Ks[l], N = Ns[l];
    int i = blockIdx.x * 256 + threadIdx.x;
    if (i >= K * N) return;
    int k = i / N, n = i % N;
    float v = W[i];
    __nv_bfloat16 hi = __float2bfloat16(v);
    float rem = v - __bfloat162float(hi);
    g_wthi[l][n * K + k] = hi;
    g_wtlo[l][n * K + k] = __float2bfloat16(rem);
}

// ---------------- dtype detection for edge_index (int32 vs int64) --------
__global__ void k_detect(const unsigned* __restrict__ w) {
    __shared__ int nz;
    if (threadIdx.x == 0) nz = 0;
    __syncthreads();
    for (int i = threadIdx.x; i < 1024; i += blockDim.x)
        if (w[2 * i + 1] != 0u) atomicAdd(&nz, 1);
    __syncthreads();
    if (threadIdx.x == 0) g_is64 = (nz == 0) ? 1 : 0;
}

__global__ void k_zero_all() {
    int i = blockIdx.x * blockDim.x + threadIdx.x;
    if (i < NN) g_deg[i] = 0;
    if (i == 0) g_counter = 0;
}

__global__ void k_build(const void* __restrict__ ed) {
    int i = blockIdx.x * blockDim.x + threadIdx.x;
    if (i >= NET) return;
    int s, d;
    if (i < NE) {
        if (g_is64) {
            const long long* p = (const long long*)ed;
            s = (int)p[i];
            d = (int)p[NE + i];
        } else {
            const int* p = (const int*)ed;
            s = p[i];
            d = p[NE + i];
        }
    } else {
        s = d = i - NE;
    }
    g_src[i] = s;
    g_dst[i] = d;
    atomicAdd(&g_deg[d], 1);
}

// warp-aggregated segment allocation (order nondeterministic, self-consistent)
__global__ void k_alloc() {
    int i = blockIdx.x * blockDim.x + threadIdx.x;
    int lane = threadIdx.x & 31;
    int v = (i < NN) ? g_deg[i] : 0;
    int incl = v;
#pragma unroll
    for (int off = 1; off < 32; off <<= 1) {
        int x = __shfl_up_sync(0xFFFFFFFFu, incl, off);
        if (lane >= off) incl += x;
    }
    int wsum = __shfl_sync(0xFFFFFFFFu, incl, 31);
    int base = 0;
    if (lane == 31) base = atomicAdd(&g_counter, wsum);
    base = __shfl_sync(0xFFFFFFFFu, base, 31);
    if (i < NN) {
        int b = base + incl - v;
        g_beg[i] = b;
        g_pos[i] = b;
    }
}

__global__ void k_fill() {
    int i = blockIdx.x * blockDim.x + threadIdx.x;
    if (i >= NET) return;
    int d = g_dst[i];
    int slot = atomicAdd(&g_pos[d], 1);
    g_csrc[slot] = g_src[i];
}

// ---------------- warp-mma helper ----------------------------------------
__device__ __forceinline__ void mma16816(float* c, uint32_t a0, uint32_t a1,
                                         uint32_t a2, uint32_t a3,
                                         uint32_t b0, uint32_t b1) {
    asm volatile(
        "mma.sync.aligned.m16n8k16.row.col.f32.bf16.bf16.f32 "
        "{%0,%1,%2,%3}, {%4,%5,%6,%7}, {%8,%9}, {%0,%1,%2,%3};"
        : "+f"(c[0]), "+f"(c[1]), "+f"(c[2]), "+f"(c[3])
        : "r"(a0), "r"(a1), "r"(a2), "r"(a3), "r"(b0), "r"(b1));
}

// ---------------- tensor-core GEMM: C[M,N] = A[M,K] @ W ------------------
// A fp32 -> bf16 hi/lo in padded smem; B = pre-split W^T[N,K] bf16 (mma col).
// D = Ahi*Bhi + Ahi*Blo + Alo*Bhi accumulated fp32 in registers.
// Epilogue: fused attention scores (pre-bias h) or fused bias (final layer).
template <int K, int N, bool SCORES, bool FINAL>
__global__ void __launch_bounds__(256)
k_mma(const float* __restrict__ A,
      const __nv_bfloat16* __restrict__ Bhi_g,
      const __nv_bfloat16* __restrict__ Blo_g,
      float* __restrict__ C,
      float* __restrict__ ssrc, float* __restrict__ sdst,
      const float* __restrict__ a_s, const float* __restrict__ a_d,
      const float* __restrict__ bias) {
    constexpr int KP   = K + 8;       // padded row stride (bf16 units)
    constexpr int A_SZ = 128 * KP;
    constexpr int B_SZ = N * KP;
    constexpr int NB   = N / 8;

    extern __shared__ __nv_bfloat16 sm[];
    __nv_bfloat16* Ahi = sm;
    __nv_bfloat16* Alo = sm + A_SZ;
    __nv_bfloat16* Bh  = sm + 2 * A_SZ;
    __nv_bfloat16* Bl  = sm + 2 * A_SZ + B_SZ;

    int tid  = threadIdx.x;
    int wid  = tid >> 5;
    int lane = tid & 31;
    int row0 = blockIdx.x * 128;

    // ---- load A tile fp32, split to bf16 hi/lo in smem ----
#pragma unroll
    for (int it = 0; it < (128 * K / 4) / 256; it++) {
        int g   = it * 256 + tid;
        int row = g / (K / 4);
        int col = (g % (K / 4)) * 4;
        float4 v = make_float4(0.f, 0.f, 0.f, 0.f);
        if (row0 + row < NN) v = *(const float4*)(A + (size_t)(row0 + row) * K + col);
        __nv_bfloat162 h01 = __floats2bfloat162_rn(v.x, v.y);
        __nv_bfloat162 h23 = __floats2bfloat162_rn(v.z, v.w);
        __nv_bfloat162 l01 = __floats2bfloat162_rn(v.x - __bfloat162float(h01.x),
                                                   v.y - __bfloat162float(h01.y));
        __nv_bfloat162 l23 = __floats2bfloat162_rn(v.z - __bfloat162float(h23.x),
                                                   v.w - __bfloat162float(h23.y));
        uint2 hv, lv;
        hv.x = *(uint32_t*)&h01; hv.y = *(uint32_t*)&h23;
        lv.x = *(uint32_t*)&l01; lv.y = *(uint32_t*)&l23;
        *(uint2*)&Ahi[row * KP + col] = hv;
        *(uint2*)&Alo[row * KP + col] = lv;
    }
    // ---- load pre-split B into padded smem ----
#pragma unroll
    for (int it = 0; it < (N * K / 8) / 256; it++) {
        int g  = it * 256 + tid;
        int n  = g / (K / 8);
        int k0 = (g % (K / 8)) * 8;
        uint4 hv = *(const uint4*)(Bhi_g + (size_t)n * K + k0);
        uint4 lv = *(const uint4*)(Blo_g + (size_t)n * K + k0);
        *(uint4*)&Bh[n * KP + k0] = hv;
        *(uint4*)&Bl[n * KP + k0] = lv;
    }
    __syncthreads();

    float acc[NB][4];
#pragma unroll
    for (int nb = 0; nb < NB; nb++)
#pragma unroll
        for (int j = 0; j < 4; j++) acc[nb][j] = 0.f;

    int rA = wid * 16 + (lane >> 2);
    int kb = (lane & 3) * 2;
    int nA = lane >> 2;

#pragma unroll
    for (int p = 0; p < 3; p++) {
        const __nv_bfloat16* Ab = (p < 2) ? Ahi : Alo;
        const __nv_bfloat16* Bb = (p == 1) ? Bl : Bh;
#pragma unroll
        for (int ks = 0; ks < K / 16; ks++) {
            int k0 = ks * 16 + kb;
            uint32_t a0 = *(const uint32_t*)&Ab[rA * KP + k0];
            uint32_t a1 = *(const uint32_t*)&Ab[(rA + 8) * KP + k0];
            uint32_t a2 = *(const uint32_t*)&Ab[rA * KP + k0 + 8];
            uint32_t a3 = *(const uint32_t*)&Ab[(rA + 8) * KP + k0 + 8];
#pragma unroll
            for (int nb = 0; nb < NB; nb++) {
                int n = nb * 8 + nA;
                uint32_t b0 = *(const uint32_t*)&Bb[n * KP + k0];
                uint32_t b1 = *(const uint32_t*)&Bb[n * KP + k0 + 8];
                mma16816(acc[nb], a0, a1, a2, a3, b0, b1);
            }
        }
    }

    // ---- epilogue ----
    int gr0 = row0 + wid * 16 + (lane >> 2);
    int gr1 = gr0 + 8;
    int cbase = (lane & 3) * 2;
    float ps0 = 0.f, pd0 = 0.f, ps1 = 0.f, pd1 = 0.f;

#pragma unroll
    for (int nb = 0; nb < NB; nb++) {
        int c = nb * 8 + cbase;
        if (SCORES) {
            float s0 = a_s[c], s1 = a_s[c + 1];
            float d0 = a_d[c], d1 = a_d[c + 1];
            ps0 += acc[nb][0] * s0 + acc[nb][1] * s1;
            pd0 += acc[nb][0] * d0 + acc[nb][1] * d1;
            ps1 += acc[nb][2] * s0 + acc[nb][3] * s1;
            pd1 += acc[nb][2] * d0 + acc[nb][3] * d1;
        }
        float bx = 0.f, by = 0.f;
        if (FINAL) { bx = bias[c]; by = bias[c + 1]; }
        if (gr0 < NN) {
            float2 v0 = make_float2(acc[nb][0] + bx, acc[nb][1] + by);
            *(float2*)(C + (size_t)gr0 * N + c) = v0;
        }
        if (gr1 < NN) {
            float2 v1 = make_float2(acc[nb][2] + bx, acc[nb][3] + by);
            *(float2*)(C + (size_t)gr1 * N + c) = v1;
        }
    }

    if (SCORES) {
#pragma unroll
        for (int off = 1; off <= 2; off <<= 1) {
            ps0 += __shfl_xor_sync(0xFFFFFFFFu, ps0, off);
            pd0 += __shfl_xor_sync(0xFFFFFFFFu, pd0, off);
            ps1 += __shfl_xor_sync(0xFFFFFFFFu, ps1, off);
            pd1 += __shfl_xor_sync(0xFFFFFFFFu, pd1, off);
        }
        if ((lane & 3) == 0) {
            if (gr0 < NN) { ssrc[gr0] = ps0; sdst[gr0] = pd0; }
            if (gr1 < NN) { ssrc[gr1] = ps1; sdst[gr1] = pd1; }
        }
    }
}

// ---------------- GAT aggregation: warp per dst node, online softmax -----
__global__ void __launch_bounds__(256)
k_agg(const float* __restrict__ h, const float* __restrict__ bias,
      float* __restrict__ out,
      const float* __restrict__ ssrc, const float* __restrict__ sdst) {
    int warp = (blockIdx.x * blockDim.x + threadIdx.x) >> 5;
    int lane = threadIdx.x & 31;
    if (warp >= NN) return;

    int beg = g_beg[warp];
    int end = beg + g_deg[warp];
    float sd = sdst[warp];

    float m = -INFINITY;
    float den = 0.f;
    float4 acc = make_float4(0.f, 0.f, 0.f, 0.f);

    for (int i = beg; i < end; i++) {
        int s = g_csrc[i];
        float e = ssrc[s] + sd;
        e = (e > 0.f) ? e : 0.2f * e;           // attention LeakyReLU
        float mn = fmaxf(m, e);
        float sc = __expf(m - mn);
        float we = __expf(e - mn);
        den = den * sc + we;
        float4 hv = *(const float4*)(h + (size_t)s * HID + lane * 4);
        acc.x = acc.x * sc + we * hv.x;
        acc.y = acc.y * sc + we * hv.y;
        acc.z = acc.z * sc + we * hv.z;
        acc.w = acc.w * sc + we * hv.w;
        m = mn;
    }

    float inv = 1.f / (den + 1e-16f);
    float4 b4 = *(const float4*)(bias + lane * 4);
    float4 v;
    v.x = acc.x * inv + b4.x;
    v.y = acc.y * inv + b4.y;
    v.z = acc.z * inv + b4.z;
    v.w = acc.w * inv + b4.w;
    v.x = (v.x > 0.f) ? v.x : 0.01f * v.x;
    v.y = (v.y > 0.f) ? v.y : 0.01f * v.y;
    v.z = (v.z > 0.f) ? v.z : 0.01f * v.z;
    v.w = (v.w > 0.f) ? v.w : 0.01f * v.w;
    *(float4*)(out + (size_t)warp * HID + lane * 4) = v;
}

// ---------------- launch -------------------------------------------------
extern "C" void kernel_launch(void* const* d_in, const int* in_sizes, int n_in,
                              void* d_out, int out_size) {
    (void)in_sizes; (void)n_in; (void)out_size;

    const float* x    = (const float*)d_in[0];
    const void*  eidx = d_in[1];

    float *p_h, *p_o, *p_ss, *p_sd;
    __nv_bfloat16 *p_whi, *p_wlo;
    cudaGetSymbolAddress((void**)&p_h, g_h);
    cudaGetSymbolAddress((void**)&p_o, g_o);
    cudaGetSymbolAddress((void**)&p_ss, g_ssrc);
    cudaGetSymbolAddress((void**)&p_sd, g_sdst);
    cudaGetSymbolAddress((void**)&p_whi, g_wthi);
    cudaGetSymbolAddress((void**)&p_wlo, g_wtlo);

    // dynamic smem: bf16 units -> bytes
    const int SZ_64_128  = (2 * 128 * 72 + 2 * 128 * 72) * 2;   //  73728
    const int SZ_128_128 = (2 * 128 * 136 + 2 * 128 * 136) * 2; // 139264
    const int SZ_128_64  = (2 * 128 * 136 + 2 * 64 * 136) * 2;  // 104448
    cudaFuncSetAttribute(k_mma<64, 128, true, false>,
                         cudaFuncAttributeMaxDynamicSharedMemorySize, SZ_64_128);
    cudaFuncSetAttribute(k_mma<128, 128, true, false>,
                         cudaFuncAttributeMaxDynamicSharedMemorySize, SZ_128_128);
    cudaFuncSetAttribute(k_mma<128, 64, false, true>,
                         cudaFuncAttributeMaxDynamicSharedMemorySize, SZ_128_64);

    // weight split/transpose (4 matrices)
    k_prepw<<<dim3(64, 4), 256>>>((const float*)d_in[2], (const float*)d_in[6],
                                  (const float*)d_in[10], (const float*)d_in[14]);

    // CSR build (once; reused by all 3 layers)
    k_detect<<<1, 256>>>((const unsigned*)eidx);
    k_zero_all<<<(NN + 255) / 256, 256>>>();
    k_build<<<(NET + 255) / 256, 256>>>(eidx);
    k_alloc<<<(NN + 255) / 256, 256>>>();
    k_fill<<<(NET + 255) / 256, 256>>>();

    const int gridM = (NN + 127) / 128;        // 391
    const int nodeBlocks = NN / 8;             // 6250 blocks * 8 warps = 50000

    for (int L = 0; L < 3; L++) {
        const float* as_ = (const float*)d_in[3 + 4 * L];
        const float* ad_ = (const float*)d_in[4 + 4 * L];
        const float* b   = (const float*)d_in[5 + 4 * L];
        float* ss = p_ss + (size_t)L * NN;
        float* sd = p_sd + (size_t)L * NN;
        const __nv_bfloat16* whi = p_whi + (size_t)L * 128 * 128;
        const __nv_bfloat16* wlo = p_wlo + (size_t)L * 128 * 128;

        if (L == 0)
            k_mma<64, 128, true, false><<<gridM, 256, SZ_64_128>>>(
                x, whi, wlo, p_h, ss, sd, as_, ad_, nullptr);
        else
            k_mma<128, 128, true, false><<<gridM, 256, SZ_128_128>>>(
                p_o, whi, wlo, p_h, ss, sd, as_, ad_, nullptr);

        k_agg<<<nodeBlocks, 256>>>(p_h, b, p_o, ss, sd);
    }

    const float* bout = (const float*)d_in[15];
    k_mma<128, 64, false, true><<<gridM, 256, SZ_128_64>>>(
        p_o, p_whi + (size_t)3 * 128 * 128, p_wlo + (size_t)3 * 128 * 128,
        (float*)d_out, nullptr, nullptr, nullptr, nullptr, bout);
}